// round 10
// baseline (speedup 1.0000x reference)
#include <cuda_runtime.h>
#include <cuda_fp16.h>
#include <cstdint>

// QKVAttention via HMMA mma.sync. qkv [32,192,2048] fp32 -> out [32,64,2048] fp32.
// S' = (Q * 0.125*log2e)^T K fp16 HMMA, P = ex2.f16x2(S'), O += P V^T fp16 HMMA.
// 16 warps (512 thr) = 8(m16) x 2(n64): small per-warp state (~115 regs) =>
// 4 warps/SMSP for latency hiding. Warp phases staggered across n-chunks.
// Row sums via ones-matrix MMA with constant B-fragment (exact fp32).
// Cross-n-half O reduction once in the epilogue.

constexpr int T  = 2048;
constexpr int CH = 64;
constexpr int BM = 128;            // queries per CTA
constexpr int BN = 128;            // keys per iteration
constexpr int NITER = T / BN;
constexpr int THREADS = 512;
constexpr int RSH = 136;           // smem row stride in halves (272 B)
constexpr int TSZ = CH * RSH * 2;  // 17408 B per [64][128] f16 tile
constexpr int OFF_K0 = TSZ;
constexpr int OFF_K1 = OFF_K0 + TSZ;
constexpr int OFF_V0 = OFF_K1 + TSZ;
constexpr int OFF_V1 = OFF_V0 + TSZ;
constexpr int SMEM_TOTAL = OFF_V1 + TSZ;   // 87040 B
// epilogue overlays (valid only after the final __syncthreads)
constexpr int OFF_OS0 = 0;                 // [64 c][132 m] f32
constexpr int OFF_OS1 = 33792;
constexpr int OFF_SUM = 67584;             // sums[2][128] f32
constexpr int OFF_INV = 68608;             // inv[128] f32
constexpr float QSCALE = 0.18033688011112042f;  // 0.125 * log2(e)

__device__ __forceinline__ uint32_t s2u(const void* p) {
    uint32_t a;
    asm("{ .reg .u64 t; cvta.to.shared.u64 t, %1; cvt.u32.u64 %0, t; }" : "=r"(a) : "l"(p));
    return a;
}
__device__ __forceinline__ void ldsm4(uint32_t* r, uint32_t a) {
    asm volatile("ldmatrix.sync.aligned.m8n8.x4.shared.b16 {%0,%1,%2,%3}, [%4];"
                 : "=r"(r[0]), "=r"(r[1]), "=r"(r[2]), "=r"(r[3]) : "r"(a));
}
__device__ __forceinline__ void ldsm4t(uint32_t* r, uint32_t a) {
    asm volatile("ldmatrix.sync.aligned.m8n8.x4.trans.shared.b16 {%0,%1,%2,%3}, [%4];"
                 : "=r"(r[0]), "=r"(r[1]), "=r"(r[2]), "=r"(r[3]) : "r"(a));
}
__device__ __forceinline__ void mma16816(float* d, const uint32_t* a, const uint32_t* b) {
    asm volatile("mma.sync.aligned.m16n8k16.row.col.f32.f16.f16.f32 "
                 "{%0,%1,%2,%3}, {%4,%5,%6,%7}, {%8,%9}, {%0,%1,%2,%3};"
                 : "+f"(d[0]), "+f"(d[1]), "+f"(d[2]), "+f"(d[3])
                 : "r"(a[0]), "r"(a[1]), "r"(a[2]), "r"(a[3]), "r"(b[0]), "r"(b[1]));
}
__device__ __forceinline__ uint32_t packh2(float lo, float hi) {
    uint32_t r; asm("cvt.rn.f16x2.f32 %0, %2, %1;" : "=r"(r) : "f"(lo), "f"(hi)); return r;
}
__device__ __forceinline__ uint32_t h2ex2(uint32_t x) {
    uint32_t y; asm("ex2.approx.f16x2 %0, %1;" : "=r"(y) : "r"(x)); return y;
}

// Load fp32 tile [64 c][128 x] (row stride T) into 4 float4 regs (512 threads).
__device__ __forceinline__ void ldg4(const float* src, int col0, int tid, float4* r) {
    #pragma unroll
    for (int it = 0; it < 4; ++it) {
        int idx = tid + it * 512;
        int c = idx >> 5, n4 = idx & 31;
        r[it] = *reinterpret_cast<const float4*>(src + (size_t)c * T + col0 + n4 * 4);
    }
}
// Convert 4 float4 -> fp16, store as [c][x] halves (row stride RSH).
__device__ __forceinline__ void cvt_sts4(const float4* r, int tid, char* dst) {
    #pragma unroll
    for (int it = 0; it < 4; ++it) {
        int idx = tid + it * 512;
        int c = idx >> 5, n4 = idx & 31;
        float4 f = r[it];
        *reinterpret_cast<uint2*>(dst + (c * RSH + n4 * 4) * 2) =
            make_uint2(packh2(f.x, f.y), packh2(f.z, f.w));
    }
}

__global__ __launch_bounds__(THREADS, 1)
void attn_hmma_kernel(const float* __restrict__ qkv, float* __restrict__ out)
{
    extern __shared__ char smem[];
    const uint32_t sb = s2u(smem);
    const int tid = threadIdx.x;
    const int lane = tid & 31, w = tid >> 5;
    const int b = blockIdx.y, t0 = blockIdx.x * BM;
    const int wm = (w >> 1) * 16;          // m16 block (8 m-warps)
    const int wn = (w & 1) * 64;           // n64 half
    const int stag = w & 3;                // phase stagger

    const float* qb = qkv + (size_t)b * 3 * CH * T;
    const float* kb = qb + CH * T;
    const float* vb = kb + CH * T;

    // ---- prologue: Q (scaled), K0, V0 -> smem fp16 ----
    {
        #pragma unroll
        for (int it = 0; it < 4; ++it) {
            int idx = tid + it * 512;
            int c = idx >> 5, n4 = idx & 31;
            float4 f = *reinterpret_cast<const float4*>(qb + (size_t)c * T + t0 + n4 * 4);
            *reinterpret_cast<uint2*>(smem + (c * RSH + n4 * 4) * 2) =
                make_uint2(packh2(f.x * QSCALE, f.y * QSCALE),
                           packh2(f.z * QSCALE, f.w * QSCALE));
        }
        float4 st0[4];
        ldg4(kb, 0, tid, st0);
        cvt_sts4(st0, tid, smem + OFF_K0);
        ldg4(vb, 0, tid, st0);
        cvt_sts4(st0, tid, smem + OFF_V0);
    }
    __syncthreads();

    // ---- per-lane ldmatrix address components ----
    const int lr = lane & 7, grp = lane >> 3;
    const int ac = lr + ((grp >= 2) ? 8 : 0);            // A(Q): c row, .trans
    const int am = (grp & 1) ? 8 : 0;
    const int kc = lr + ((grp & 1) ? 8 : 0);             // B(K): c row, .trans
    const int kn = (grp >= 2) ? 8 : 0;
    const int vc = lr + ((grp >= 2) ? 8 : 0);            // B(V): c row, non-trans
    const int vn = (grp & 1) ? 8 : 0;

    // constant B-fragment of the ones matrix (col 0 all-ones): rowsum MMA
    uint32_t ones2[2];
    ones2[0] = ones2[1] = (lane < 4) ? 0x3C003C00u : 0u;

    // ---- preload Q A-fragments (loop invariant): 4 k-steps over c ----
    uint32_t qa[4][4];
    #pragma unroll
    for (int kk = 0; kk < 4; ++kk)
        ldsm4t(qa[kk], sb + ((kk * 16 + ac) * RSH + wm + am) * 2);

    float o[8][4];
    #pragma unroll
    for (int j = 0; j < 8; ++j) o[j][0] = o[j][1] = o[j][2] = o[j][3] = 0.f;
    float oe[4] = {0.f, 0.f, 0.f, 0.f};

    float4 st[4];
    for (int i = 0; i < NITER; ++i) {
        const int cur = i & 1, nxt = cur ^ 1;
        const bool more = (i + 1 < NITER);
        const uint32_t Kb = sb + OFF_K0 + cur * TSZ;
        const uint32_t Vb = sb + OFF_V0 + cur * TSZ;

        if (more) ldg4(kb, (i + 1) * BN, tid, st);   // K(i+1) into regs

        #pragma unroll
        for (int nn = 0; nn < 4; ++nn) {
            const int nnr = (nn + stag) & 3;         // staggered chunk
            const int ncol = wn + nnr * 16;

            // ---- S chunk: m16 x n16 ----
            float s[2][4];
            s[0][0]=s[0][1]=s[0][2]=s[0][3]=0.f;
            s[1][0]=s[1][1]=s[1][2]=s[1][3]=0.f;
            #pragma unroll
            for (int kk = 0; kk < 4; ++kk) {
                uint32_t kb4[4];
                ldsm4t(kb4, Kb + ((kk * 16 + kc) * RSH + ncol + kn) * 2);
                mma16816(s[0], qa[kk], kb4);
                mma16816(s[1], qa[kk], kb4 + 2);
            }

            // ---- P = ex2(S) f16x2, pack to A-fragment; rowsum via ones-MMA ----
            uint32_t pa[4];
            pa[0] = h2ex2(packh2(s[0][0], s[0][1]));
            pa[1] = h2ex2(packh2(s[0][2], s[0][3]));
            pa[2] = h2ex2(packh2(s[1][0], s[1][1]));
            pa[3] = h2ex2(packh2(s[1][2], s[1][3]));
            mma16816(oe, pa, ones2);

            // ---- PV chunk: O += P[:, n16] V^T[n16, :] ----
            #pragma unroll
            for (int cc = 0; cc < 4; ++cc) {
                uint32_t vb4[4];
                ldsm4(vb4, Vb + ((cc * 16 + vc) * RSH + ncol + vn) * 2);
                mma16816(o[2 * cc],     pa, vb4);
                mma16816(o[2 * cc + 1], pa, vb4 + 2);
            }

            if (nn == 1 && more) {
                cvt_sts4(st, tid, smem + OFF_K0 + nxt * TSZ);   // K(i+1) -> smem
                ldg4(vb, (i + 1) * BN, tid, st);                // V(i+1) into regs
            }
        }
        if (more) cvt_sts4(st, tid, smem + OFF_V0 + nxt * TSZ);
        __syncthreads();   // publish nxt buffers; all reads of cur complete
    }

    // ---- epilogue: cross-half reduction + normalize + store ----
    {
        // partial O -> Os[n-half] (c-major, stride 132, conflict-free scalar stores)
        float* Os = reinterpret_cast<float*>(smem + ((w & 1) ? OFF_OS1 : OFF_OS0));
        const int cq = 2 * (lane & 3);
        const int r0 = wm + (lane >> 2), r1 = r0 + 8;
        #pragma unroll
        for (int j = 0; j < 8; ++j) {
            const int c = (j >> 1) * 16 + (j & 1) * 8 + cq;
            Os[c * 132 + r0]       = o[j][0];
            Os[(c + 1) * 132 + r0] = o[j][1];
            Os[c * 132 + r1]       = o[j][2];
            Os[(c + 1) * 132 + r1] = o[j][3];
        }
        // partial row sums
        float* SU = reinterpret_cast<float*>(smem + OFF_SUM) + (w & 1) * 128;
        if ((lane & 3) == 0) {
            SU[r0]     = oe[0];
            SU[r0 + 8] = oe[2];
        }
        __syncthreads();

        float* S0 = reinterpret_cast<float*>(smem + OFF_SUM);
        float* IV = reinterpret_cast<float*>(smem + OFF_INV);
        if (tid < 128) IV[tid] = 1.0f / (S0[tid] + S0[128 + tid]);
        __syncthreads();

        const float* Os0 = reinterpret_cast<const float*>(smem + OFF_OS0);
        const float* Os1 = reinterpret_cast<const float*>(smem + OFF_OS1);
        float* ob = out + (size_t)b * CH * T;
        #pragma unroll
        for (int it = 0; it < 4; ++it) {
            int idx = tid + it * 512;
            int c = idx >> 5, m4 = idx & 31;
            float4 a = *reinterpret_cast<const float4*>(&Os0[c * 132 + m4 * 4]);
            float4 d = *reinterpret_cast<const float4*>(&Os1[c * 132 + m4 * 4]);
            float4 iv = *reinterpret_cast<const float4*>(&IV[m4 * 4]);
            float4 r = make_float4((a.x + d.x) * iv.x, (a.y + d.y) * iv.y,
                                   (a.z + d.z) * iv.z, (a.w + d.w) * iv.w);
            *reinterpret_cast<float4*>(ob + (size_t)c * T + t0 + m4 * 4) = r;
        }
    }
}

extern "C" void kernel_launch(void* const* d_in, const int* in_sizes, int n_in,
                              void* d_out, int out_size)
{
    (void)in_sizes; (void)n_in; (void)out_size;
    const float* qkv = (const float*)d_in[0];
    float* out = (float*)d_out;

    cudaFuncSetAttribute(attn_hmma_kernel,
                         cudaFuncAttributeMaxDynamicSharedMemorySize, SMEM_TOTAL);
    dim3 grid(T / BM, 32);
    attn_hmma_kernel<<<grid, THREADS, SMEM_TOTAL>>>(qkv, out);
}

// round 12
// speedup vs baseline: 1.0825x; 1.0825x over previous
#include <cuda_runtime.h>
#include <cuda_fp16.h>
#include <cstdint>

// QKVAttention via HMMA mma.sync. qkv [32,192,2048] fp32 -> out [32,64,2048] fp32.
// Pre-pass converts qkv to fp16 once (Q pre-scaled by 0.125*log2e) into __device__
// scratch -- removes the 16x-redundant per-CTA fp32 load+convert. Main kernel
// streams K/V fp16 tiles via cp.async (double-buffered), S' = Q^T K fp16 HMMA,
// P = ex2.f16x2(S'), O += P V^T fp16 HMMA, rowsums via ones-matrix MMA.

constexpr int T  = 2048;
constexpr int CH = 64;
constexpr int BM = 128;            // queries per CTA
constexpr int BN = 128;            // keys per iteration
constexpr int NITER = T / BN;
constexpr int THREADS = 512;
constexpr int RSH = 136;           // smem row stride in halves (272 B)
constexpr int TSZ = CH * RSH * 2;  // 17408 B per [64][128] f16 tile
constexpr int OFF_K0 = TSZ;
constexpr int OFF_K1 = OFF_K0 + TSZ;
constexpr int OFF_V0 = OFF_K1 + TSZ;
constexpr int OFF_V1 = OFF_V0 + TSZ;
constexpr int SMEM_TOTAL = OFF_V1 + TSZ;   // 87040 B
// epilogue overlays
constexpr int OFF_OS0 = 0;                 // [64 c][132 m] f32
constexpr int OFF_OS1 = 33792;
constexpr int OFF_SUM = 67584;             // sums[2][128] f32
constexpr int OFF_INV = 68608;             // inv[128] f32
constexpr float QSCALE = 0.18033688011112042f;  // 0.125 * log2(e)

__device__ __half g_qkv16[(size_t)32 * 192 * 2048];   // fp16 scratch (25.2 MB)

__device__ __forceinline__ uint32_t s2u(const void* p) {
    uint32_t a;
    asm("{ .reg .u64 t; cvta.to.shared.u64 t, %1; cvt.u32.u64 %0, t; }" : "=r"(a) : "l"(p));
    return a;
}
__device__ __forceinline__ void ldsm4(uint32_t* r, uint32_t a) {
    asm volatile("ldmatrix.sync.aligned.m8n8.x4.shared.b16 {%0,%1,%2,%3}, [%4];"
                 : "=r"(r[0]), "=r"(r[1]), "=r"(r[2]), "=r"(r[3]) : "r"(a));
}
__device__ __forceinline__ void ldsm4t(uint32_t* r, uint32_t a) {
    asm volatile("ldmatrix.sync.aligned.m8n8.x4.trans.shared.b16 {%0,%1,%2,%3}, [%4];"
                 : "=r"(r[0]), "=r"(r[1]), "=r"(r[2]), "=r"(r[3]) : "r"(a));
}
__device__ __forceinline__ void mma16816(float* d, const uint32_t* a, const uint32_t* b) {
    asm volatile("mma.sync.aligned.m16n8k16.row.col.f32.f16.f16.f32 "
                 "{%0,%1,%2,%3}, {%4,%5,%6,%7}, {%8,%9}, {%0,%1,%2,%3};"
                 : "+f"(d[0]), "+f"(d[1]), "+f"(d[2]), "+f"(d[3])
                 : "r"(a[0]), "r"(a[1]), "r"(a[2]), "r"(a[3]), "r"(b[0]), "r"(b[1]));
}
__device__ __forceinline__ uint32_t packh2(float lo, float hi) {
    uint32_t r; asm("cvt.rn.f16x2.f32 %0, %2, %1;" : "=r"(r) : "f"(lo), "f"(hi)); return r;
}
__device__ __forceinline__ uint32_t h2ex2(uint32_t x) {
    uint32_t y; asm("ex2.approx.f16x2 %0, %1;" : "=r"(y) : "r"(x)); return y;
}
// cp.async a [64 c][128 x] fp16 tile (row stride T halves) into RSH-strided smem.
__device__ __forceinline__ void cp_tile(const __half* src, uint32_t dst_s, int tid) {
    #pragma unroll
    for (int it = 0; it < 2; ++it) {
        int idx = tid + it * 512;
        int row = idx >> 4, c16 = idx & 15;   // 16 x 16B per 256B row
        uint32_t d = dst_s + (row * RSH + c16 * 8) * 2;
        const void* s = src + (size_t)row * T + c16 * 8;
        asm volatile("cp.async.cg.shared.global [%0], [%1], 16;" :: "r"(d), "l"(s));
    }
}
__device__ __forceinline__ void cp_commit() {
    asm volatile("cp.async.commit_group;" ::: "memory");
}
__device__ __forceinline__ void cp_wait0() {
    asm volatile("cp.async.wait_group 0;" ::: "memory");
}

// ---- pre-pass: fp32 -> fp16, Q rows scaled ----
__global__ __launch_bounds__(256)
void cvt_kernel(const float* __restrict__ qkv, __half* __restrict__ dst)
{
    size_t base = ((size_t)blockIdx.x * 256 + threadIdx.x) * 8;
    int row = (int)((base >> 11) % 192);           // row within batch (T=2048)
    float sc = (row < 64) ? QSCALE : 1.0f;
    float4 f0 = *reinterpret_cast<const float4*>(qkv + base);
    float4 f1 = *reinterpret_cast<const float4*>(qkv + base + 4);
    uint4 h;
    h.x = packh2(f0.x * sc, f0.y * sc);
    h.y = packh2(f0.z * sc, f0.w * sc);
    h.z = packh2(f1.x * sc, f1.y * sc);
    h.w = packh2(f1.z * sc, f1.w * sc);
    *reinterpret_cast<uint4*>(dst + base) = h;
}

__global__ __launch_bounds__(THREADS, 1)
void attn_hmma_kernel(const float* __restrict__ qkv, float* __restrict__ out)
{
    extern __shared__ char smem[];
    const uint32_t sb = s2u(smem);
    const int tid = threadIdx.x;
    const int lane = tid & 31, w = tid >> 5;
    const int b = blockIdx.y, t0 = blockIdx.x * BM;
    const int wm = (w >> 1) * 16;          // m16 block (8 m-warps)
    const int wn = (w & 1) * 64;           // n64 half
    const int stag = w & 3;                // phase stagger
    (void)qkv;

    const __half* qh = g_qkv16 + (size_t)b * 3 * CH * T;
    const __half* kh = qh + CH * T;
    const __half* vh = kh + CH * T;

    // ---- prologue: Q, K0, V0 tiles via cp.async ----
    cp_tile(qh + t0, sb, tid);
    cp_tile(kh, sb + OFF_K0, tid);
    cp_tile(vh, sb + OFF_V0, tid);
    cp_commit();
    cp_wait0();
    __syncthreads();

    // ---- per-lane ldmatrix address components ----
    const int lr = lane & 7, grp = lane >> 3;
    const int ac = lr + ((grp >= 2) ? 8 : 0);            // A(Q): c row, .trans
    const int am = (grp & 1) ? 8 : 0;
    const int kc = lr + ((grp & 1) ? 8 : 0);             // B(K): c row, .trans
    const int kn = (grp >= 2) ? 8 : 0;
    const int vc = lr + ((grp >= 2) ? 8 : 0);            // B(V): c row, non-trans
    const int vn = (grp & 1) ? 8 : 0;

    // constant B-fragment of the ones matrix (col 0 all-ones): rowsum MMA
    uint32_t ones2[2];
    ones2[0] = ones2[1] = (lane < 4) ? 0x3C003C00u : 0u;

    // ---- preload Q A-fragments (loop invariant): 4 k-steps over c ----
    uint32_t qa[4][4];
    #pragma unroll
    for (int kk = 0; kk < 4; ++kk)
        ldsm4t(qa[kk], sb + ((kk * 16 + ac) * RSH + wm + am) * 2);

    float o[8][4];
    #pragma unroll
    for (int j = 0; j < 8; ++j) o[j][0] = o[j][1] = o[j][2] = o[j][3] = 0.f;
    float oe[4] = {0.f, 0.f, 0.f, 0.f};

    for (int i = 0; i < NITER; ++i) {
        const int cur = i & 1, nxt = cur ^ 1;
        const bool more = (i + 1 < NITER);
        const uint32_t Kb = sb + OFF_K0 + cur * TSZ;
        const uint32_t Vb = sb + OFF_V0 + cur * TSZ;

        if (more) {   // start K/V(i+1) loads (overlap with this iter's compute)
            cp_tile(kh + (i + 1) * BN, sb + OFF_K0 + nxt * TSZ, tid);
            cp_tile(vh + (i + 1) * BN, sb + OFF_V0 + nxt * TSZ, tid);
            cp_commit();
        }

        #pragma unroll
        for (int nn = 0; nn < 4; ++nn) {
            const int nnr = (nn + stag) & 3;         // staggered chunk
            const int ncol = wn + nnr * 16;

            // ---- S chunk: m16 x n16 ----
            float s[2][4];
            s[0][0]=s[0][1]=s[0][2]=s[0][3]=0.f;
            s[1][0]=s[1][1]=s[1][2]=s[1][3]=0.f;
            #pragma unroll
            for (int kk = 0; kk < 4; ++kk) {
                uint32_t kb4[4];
                ldsm4t(kb4, Kb + ((kk * 16 + kc) * RSH + ncol + kn) * 2);
                mma16816(s[0], qa[kk], kb4);
                mma16816(s[1], qa[kk], kb4 + 2);
            }

            // ---- P = ex2(S) f16x2, pack to A-fragment; rowsum via ones-MMA ----
            uint32_t pa[4];
            pa[0] = h2ex2(packh2(s[0][0], s[0][1]));
            pa[1] = h2ex2(packh2(s[0][2], s[0][3]));
            pa[2] = h2ex2(packh2(s[1][0], s[1][1]));
            pa[3] = h2ex2(packh2(s[1][2], s[1][3]));
            mma16816(oe, pa, ones2);

            // ---- PV chunk: O += P[:, n16] V^T[n16, :] ----
            #pragma unroll
            for (int cc = 0; cc < 4; ++cc) {
                uint32_t vb4[4];
                ldsm4(vb4, Vb + ((cc * 16 + vc) * RSH + ncol + vn) * 2);
                mma16816(o[2 * cc],     pa, vb4);
                mma16816(o[2 * cc + 1], pa, vb4 + 2);
            }
        }

        if (more) cp_wait0();   // K/V(i+1) landed
        __syncthreads();        // all reads of cur done; nxt published
    }

    // ---- epilogue: cross-half reduction + normalize + store ----
    {
        float* Os = reinterpret_cast<float*>(smem + ((w & 1) ? OFF_OS1 : OFF_OS0));
        const int cq = 2 * (lane & 3);
        const int r0 = wm + (lane >> 2), r1 = r0 + 8;
        #pragma unroll
        for (int j = 0; j < 8; ++j) {
            const int c = (j >> 1) * 16 + (j & 1) * 8 + cq;
            Os[c * 132 + r0]       = o[j][0];
            Os[(c + 1) * 132 + r0] = o[j][1];
            Os[c * 132 + r1]       = o[j][2];
            Os[(c + 1) * 132 + r1] = o[j][3];
        }
        float* SU = reinterpret_cast<float*>(smem + OFF_SUM) + (w & 1) * 128;
        if ((lane & 3) == 0) {
            SU[r0]     = oe[0];
            SU[r0 + 8] = oe[2];
        }
        __syncthreads();

        float* S0 = reinterpret_cast<float*>(smem + OFF_SUM);
        float* IV = reinterpret_cast<float*>(smem + OFF_INV);
        if (tid < 128) IV[tid] = 1.0f / (S0[tid] + S0[128 + tid]);
        __syncthreads();

        const float* Os0 = reinterpret_cast<const float*>(smem + OFF_OS0);
        const float* Os1 = reinterpret_cast<const float*>(smem + OFF_OS1);
        float* ob = out + (size_t)b * CH * T;
        #pragma unroll
        for (int it = 0; it < 4; ++it) {
            int idx = tid + it * 512;
            int c = idx >> 5, m4 = idx & 31;
            float4 a = *reinterpret_cast<const float4*>(&Os0[c * 132 + m4 * 4]);
            float4 d = *reinterpret_cast<const float4*>(&Os1[c * 132 + m4 * 4]);
            float4 iv = *reinterpret_cast<const float4*>(&IV[m4 * 4]);
            float4 r = make_float4((a.x + d.x) * iv.x, (a.y + d.y) * iv.y,
                                   (a.z + d.z) * iv.z, (a.w + d.w) * iv.w);
            *reinterpret_cast<float4*>(ob + (size_t)c * T + t0 + m4 * 4) = r;
        }
    }
}

extern "C" void kernel_launch(void* const* d_in, const int* in_sizes, int n_in,
                              void* d_out, int out_size)
{
    (void)in_sizes; (void)n_in; (void)out_size;
    const float* qkv = (const float*)d_in[0];
    float* out = (float*)d_out;

    __half* scratch = nullptr;
    cudaGetSymbolAddress((void**)&scratch, g_qkv16);

    cudaFuncSetAttribute(attn_hmma_kernel,
                         cudaFuncAttributeMaxDynamicSharedMemorySize, SMEM_TOTAL);

    // pre-pass: 12.58M elems, 8 per thread, 256 thr -> 6144 blocks
    cvt_kernel<<<6144, 256>>>(qkv, scratch);
    dim3 grid(T / BM, 32);
    attn_hmma_kernel<<<grid, THREADS, SMEM_TOTAL>>>(qkv, out);
}

// round 14
// speedup vs baseline: 1.1067x; 1.0224x over previous
#include <cuda_runtime.h>
#include <cuda_fp16.h>
#include <cstdint>

// QKVAttention via HMMA mma.sync. qkv [32,192,2048] fp32 -> out [32,64,2048] fp32.
// Pre-pass converts K,V to fp16 once into __device__ scratch (L2-resident).
// Main kernel: BM=64 queries/CTA, 256 thr, 8 warps = 4(m16) x 2(n64); 2 CTAs/SM
// so barrier phases of one CTA overlap MMA of the other; 1024 CTAs -> 98.8% SM
// balance. Q converted in-CTA (scaled by 0.125*log2e). K/V tiles stream via
// cp.async double-buffered. S' = Q^T K fp16 HMMA, P = ex2.f16x2(S'),
// O += P V^T fp16 HMMA, rowsums via ones-matrix MMA (exact fp32).

constexpr int T  = 2048;
constexpr int CH = 64;
constexpr int BM = 64;             // queries per CTA
constexpr int BN = 128;            // keys per iteration
constexpr int NITER = T / BN;
constexpr int THREADS = 256;
constexpr int RSQ = 72;            // Q smem row stride (halves): (addr/16)%8 distinct
constexpr int RSH = 136;           // K/V smem row stride (halves)
constexpr int QSZ = CH * RSQ * 2;  // 9216 B
constexpr int TSZ = CH * RSH * 2;  // 17408 B per [64][128] f16 tile
constexpr int OFF_K0 = QSZ;
constexpr int OFF_K1 = OFF_K0 + TSZ;
constexpr int OFF_V0 = OFF_K1 + TSZ;
constexpr int OFF_V1 = OFF_V0 + TSZ;
constexpr int SMEM_TOTAL = OFF_V1 + TSZ;   // 78848 B -> 2 CTAs/SM
// epilogue overlays (valid after final __syncthreads)
constexpr int OFF_OS0 = 0;                 // [64 c][68 m] f32 = 17408
constexpr int OFF_OS1 = 17408;
constexpr int OFF_SUM = 34816;             // sums[2][64] f32
constexpr int OFF_INV = 35328;             // inv[64] f32
constexpr float QSCALE = 0.18033688011112042f;  // 0.125 * log2(e)

__device__ __half g_qkv16[(size_t)32 * 192 * 2048];   // fp16 scratch (K/V regions used)

__device__ __forceinline__ uint32_t s2u(const void* p) {
    uint32_t a;
    asm("{ .reg .u64 t; cvta.to.shared.u64 t, %1; cvt.u32.u64 %0, t; }" : "=r"(a) : "l"(p));
    return a;
}
__device__ __forceinline__ void ldsm4(uint32_t* r, uint32_t a) {
    asm volatile("ldmatrix.sync.aligned.m8n8.x4.shared.b16 {%0,%1,%2,%3}, [%4];"
                 : "=r"(r[0]), "=r"(r[1]), "=r"(r[2]), "=r"(r[3]) : "r"(a));
}
__device__ __forceinline__ void ldsm4t(uint32_t* r, uint32_t a) {
    asm volatile("ldmatrix.sync.aligned.m8n8.x4.trans.shared.b16 {%0,%1,%2,%3}, [%4];"
                 : "=r"(r[0]), "=r"(r[1]), "=r"(r[2]), "=r"(r[3]) : "r"(a));
}
__device__ __forceinline__ void mma16816(float* d, const uint32_t* a, const uint32_t* b) {
    asm volatile("mma.sync.aligned.m16n8k16.row.col.f32.f16.f16.f32 "
                 "{%0,%1,%2,%3}, {%4,%5,%6,%7}, {%8,%9}, {%0,%1,%2,%3};"
                 : "+f"(d[0]), "+f"(d[1]), "+f"(d[2]), "+f"(d[3])
                 : "r"(a[0]), "r"(a[1]), "r"(a[2]), "r"(a[3]), "r"(b[0]), "r"(b[1]));
}
__device__ __forceinline__ uint32_t packh2(float lo, float hi) {
    uint32_t r; asm("cvt.rn.f16x2.f32 %0, %2, %1;" : "=r"(r) : "f"(lo), "f"(hi)); return r;
}
__device__ __forceinline__ uint32_t h2ex2(uint32_t x) {
    uint32_t y; asm("ex2.approx.f16x2 %0, %1;" : "=r"(y) : "r"(x)); return y;
}
// cp.async a [64 c][128 x] fp16 tile (row stride T halves) into RSH-strided smem.
__device__ __forceinline__ void cp_tile(const __half* src, uint32_t dst_s, int tid) {
    #pragma unroll
    for (int it = 0; it < 4; ++it) {
        int idx = tid + it * 256;
        int row = idx >> 4, c16 = idx & 15;   // 16 x 16B per row
        uint32_t d = dst_s + (row * RSH + c16 * 8) * 2;
        const void* s = src + (size_t)row * T + c16 * 8;
        asm volatile("cp.async.cg.shared.global [%0], [%1], 16;" :: "r"(d), "l"(s));
    }
}
__device__ __forceinline__ void cp_commit() {
    asm volatile("cp.async.commit_group;" ::: "memory");
}
__device__ __forceinline__ void cp_wait0() {
    asm volatile("cp.async.wait_group 0;" ::: "memory");
}

// ---- pre-pass: K,V fp32 -> fp16 (rows 64..191 of each batch) ----
__global__ __launch_bounds__(256)
void cvt_kernel(const float* __restrict__ qkv, __half* __restrict__ dst)
{
    size_t idx8 = ((size_t)blockIdx.x * 256 + threadIdx.x) * 8;   // over K/V elems
    size_t bt = idx8 / (128 * 2048);                               // batch
    size_t rem = idx8 % (128 * 2048);
    size_t off = bt * (192 * 2048) + 64 * 2048 + rem;
    float4 f0 = *reinterpret_cast<const float4*>(qkv + off);
    float4 f1 = *reinterpret_cast<const float4*>(qkv + off + 4);
    uint4 h;
    h.x = packh2(f0.x, f0.y);
    h.y = packh2(f0.z, f0.w);
    h.z = packh2(f1.x, f1.y);
    h.w = packh2(f1.z, f1.w);
    *reinterpret_cast<uint4*>(dst + off) = h;
}

__global__ __launch_bounds__(THREADS, 2)
void attn_hmma_kernel(const float* __restrict__ qkv, float* __restrict__ out)
{
    extern __shared__ char smem[];
    const uint32_t sb = s2u(smem);
    const int tid = threadIdx.x;
    const int lane = tid & 31, w = tid >> 5;
    const int b = blockIdx.y, t0 = blockIdx.x * BM;
    const int wm = (w >> 1) * 16;          // m16 block (4 m-warps)
    const int wn = (w & 1) * 64;           // n64 half
    const int stag = w & 3;                // phase stagger

    const float* qb = qkv + (size_t)b * 3 * CH * T;
    const __half* kh = g_qkv16 + (size_t)b * 3 * CH * T + (size_t)CH * T;
    const __half* vh = kh + (size_t)CH * T;

    // ---- prologue: K0/V0 via cp.async; Q fp32 -> scaled fp16 smem ----
    cp_tile(kh, sb + OFF_K0, tid);
    cp_tile(vh, sb + OFF_V0, tid);
    cp_commit();
    #pragma unroll
    for (int it = 0; it < 4; ++it) {
        int idx = tid + it * 256;
        int c = idx >> 4, m4 = idx & 15;   // [64 c][16 float4 of m]
        float4 f = *reinterpret_cast<const float4*>(qb + (size_t)c * T + t0 + m4 * 4);
        *reinterpret_cast<uint2*>(smem + (c * RSQ + m4 * 4) * 2) =
            make_uint2(packh2(f.x * QSCALE, f.y * QSCALE),
                       packh2(f.z * QSCALE, f.w * QSCALE));
    }
    cp_wait0();
    __syncthreads();

    // ---- per-lane ldmatrix address components ----
    const int lr = lane & 7, grp = lane >> 3;
    const int ac = lr + ((grp >= 2) ? 8 : 0);            // A(Q): c row, .trans
    const int am = (grp & 1) ? 8 : 0;
    const int kc = lr + ((grp & 1) ? 8 : 0);             // B(K): c row, .trans
    const int kn = (grp >= 2) ? 8 : 0;
    const int vc = lr + ((grp >= 2) ? 8 : 0);            // B(V): c row, non-trans
    const int vn = (grp & 1) ? 8 : 0;

    // constant B-fragment of the ones matrix (col 0 all-ones): rowsum MMA
    uint32_t ones2[2];
    ones2[0] = ones2[1] = (lane < 4) ? 0x3C003C00u : 0u;

    // ---- preload Q A-fragments (loop invariant): 4 k-steps over c ----
    uint32_t qa[4][4];
    #pragma unroll
    for (int kk = 0; kk < 4; ++kk)
        ldsm4t(qa[kk], sb + ((kk * 16 + ac) * RSQ + wm + am) * 2);

    float o[8][4];
    #pragma unroll
    for (int j = 0; j < 8; ++j) o[j][0] = o[j][1] = o[j][2] = o[j][3] = 0.f;
    float oe[4] = {0.f, 0.f, 0.f, 0.f};

    for (int i = 0; i < NITER; ++i) {
        const int cur = i & 1, nxt = cur ^ 1;
        const bool more = (i + 1 < NITER);
        const uint32_t Kb = sb + OFF_K0 + cur * TSZ;
        const uint32_t Vb = sb + OFF_V0 + cur * TSZ;

        if (more) {   // start K/V(i+1) loads (overlap with this iter's compute)
            cp_tile(kh + (i + 1) * BN, sb + OFF_K0 + nxt * TSZ, tid);
            cp_tile(vh + (i + 1) * BN, sb + OFF_V0 + nxt * TSZ, tid);
            cp_commit();
        }

        #pragma unroll
        for (int nn = 0; nn < 4; ++nn) {
            const int nnr = (nn + stag) & 3;         // staggered chunk
            const int ncol = wn + nnr * 16;

            // ---- S chunk: m16 x n16 ----
            float s[2][4];
            s[0][0]=s[0][1]=s[0][2]=s[0][3]=0.f;
            s[1][0]=s[1][1]=s[1][2]=s[1][3]=0.f;
            #pragma unroll
            for (int kk = 0; kk < 4; ++kk) {
                uint32_t kb4[4];
                ldsm4t(kb4, Kb + ((kk * 16 + kc) * RSH + ncol + kn) * 2);
                mma16816(s[0], qa[kk], kb4);
                mma16816(s[1], qa[kk], kb4 + 2);
            }

            // ---- P = ex2(S) f16x2, pack to A-fragment; rowsum via ones-MMA ----
            uint32_t pa[4];
            pa[0] = h2ex2(packh2(s[0][0], s[0][1]));
            pa[1] = h2ex2(packh2(s[0][2], s[0][3]));
            pa[2] = h2ex2(packh2(s[1][0], s[1][1]));
            pa[3] = h2ex2(packh2(s[1][2], s[1][3]));
            mma16816(oe, pa, ones2);

            // ---- PV chunk: O += P[:, n16] V^T[n16, :] ----
            #pragma unroll
            for (int cc = 0; cc < 4; ++cc) {
                uint32_t vb4[4];
                ldsm4(vb4, Vb + ((cc * 16 + vc) * RSH + ncol + vn) * 2);
                mma16816(o[2 * cc],     pa, vb4);
                mma16816(o[2 * cc + 1], pa, vb4 + 2);
            }
        }

        if (more) cp_wait0();   // K/V(i+1) landed
        __syncthreads();        // all reads of cur done; nxt published
    }

    // ---- epilogue: cross-half reduction + normalize + store ----
    {
        float* Os = reinterpret_cast<float*>(smem + ((w & 1) ? OFF_OS1 : OFF_OS0));
        const int cq = 2 * (lane & 3);
        const int r0 = wm + (lane >> 2), r1 = r0 + 8;
        #pragma unroll
        for (int j = 0; j < 8; ++j) {
            const int c = (j >> 1) * 16 + (j & 1) * 8 + cq;
            Os[c * 68 + r0]       = o[j][0];
            Os[(c + 1) * 68 + r0] = o[j][1];
            Os[c * 68 + r1]       = o[j][2];
            Os[(c + 1) * 68 + r1] = o[j][3];
        }
        float* SU = reinterpret_cast<float*>(smem + OFF_SUM) + (w & 1) * 64;
        if ((lane & 3) == 0) {
            SU[r0]     = oe[0];
            SU[r0 + 8] = oe[2];
        }
        __syncthreads();

        float* S0 = reinterpret_cast<float*>(smem + OFF_SUM);
        float* IV = reinterpret_cast<float*>(smem + OFF_INV);
        if (tid < 64) IV[tid] = 1.0f / (S0[tid] + S0[64 + tid]);
        __syncthreads();

        const float* Os0 = reinterpret_cast<const float*>(smem + OFF_OS0);
        const float* Os1 = reinterpret_cast<const float*>(smem + OFF_OS1);
        float* ob = out + (size_t)b * CH * T;
        #pragma unroll
        for (int it = 0; it < 4; ++it) {
            int idx = tid + it * 256;
            int c = idx >> 4, m4 = idx & 15;
            float4 a = *reinterpret_cast<const float4*>(&Os0[c * 68 + m4 * 4]);
            float4 d = *reinterpret_cast<const float4*>(&Os1[c * 68 + m4 * 4]);
            float4 iv = *reinterpret_cast<const float4*>(&IV[m4 * 4]);
            float4 r = make_float4((a.x + d.x) * iv.x, (a.y + d.y) * iv.y,
                                   (a.z + d.z) * iv.z, (a.w + d.w) * iv.w);
            *reinterpret_cast<float4*>(ob + (size_t)c * T + t0 + m4 * 4) = r;
        }
    }
}

extern "C" void kernel_launch(void* const* d_in, const int* in_sizes, int n_in,
                              void* d_out, int out_size)
{
    (void)in_sizes; (void)n_in; (void)out_size;
    const float* qkv = (const float*)d_in[0];
    float* out = (float*)d_out;

    __half* scratch = nullptr;
    cudaGetSymbolAddress((void**)&scratch, g_qkv16);

    cudaFuncSetAttribute(attn_hmma_kernel,
                         cudaFuncAttributeMaxDynamicSharedMemorySize, SMEM_TOTAL);

    // pre-pass: K/V only: 32*128*2048 = 8.39M elems, 8/thread, 256 thr -> 4096 blocks
    cvt_kernel<<<4096, 256>>>(qkv, scratch);
    dim3 grid(T / BM, 32);
    attn_hmma_kernel<<<grid, THREADS, SMEM_TOTAL>>>(qkv, out);
}

// round 15
// speedup vs baseline: 1.1070x; 1.0003x over previous
#include <cuda_runtime.h>
#include <cuda_fp16.h>
#include <cstdint>

// QKVAttention via HMMA mma.sync. qkv [32,192,2048] fp32 -> out [32,64,2048] fp32.
// Pre-pass converts K,V to fp16 once into __device__ scratch (L2-resident).
// Main: BM=64/CTA, 256 thr, 8 warps = 4(m16) x 2(n64), 2 CTAs/SM, cp.async K/V.
// Per-warp software pipeline: S(chunk n+1) mma issue overlapped with PV(chunk n)
// mma (independent chains) so the tensor pipe stays fed through the exp window.

constexpr int T  = 2048;
constexpr int CH = 64;
constexpr int BM = 64;             // queries per CTA
constexpr int BN = 128;            // keys per iteration
constexpr int NITER = T / BN;
constexpr int THREADS = 256;
constexpr int RSQ = 72;            // Q smem row stride (halves)
constexpr int RSH = 136;           // K/V smem row stride (halves)
constexpr int QSZ = CH * RSQ * 2;  // 9216 B
constexpr int TSZ = CH * RSH * 2;  // 17408 B per [64][128] f16 tile
constexpr int OFF_K0 = QSZ;
constexpr int OFF_K1 = OFF_K0 + TSZ;
constexpr int OFF_V0 = OFF_K1 + TSZ;
constexpr int OFF_V1 = OFF_V0 + TSZ;
constexpr int SMEM_TOTAL = OFF_V1 + TSZ;   // 78848 B -> 2 CTAs/SM
// epilogue overlays
constexpr int OFF_OS0 = 0;                 // [64 c][68 m] f32
constexpr int OFF_OS1 = 17408;
constexpr int OFF_SUM = 34816;             // sums[2][64] f32
constexpr int OFF_INV = 35328;             // inv[64] f32
constexpr float QSCALE = 0.18033688011112042f;  // 0.125 * log2(e)

__device__ __half g_qkv16[(size_t)32 * 192 * 2048];

__device__ __forceinline__ uint32_t s2u(const void* p) {
    uint32_t a;
    asm("{ .reg .u64 t; cvta.to.shared.u64 t, %1; cvt.u32.u64 %0, t; }" : "=r"(a) : "l"(p));
    return a;
}
__device__ __forceinline__ void ldsm4(uint32_t* r, uint32_t a) {
    asm volatile("ldmatrix.sync.aligned.m8n8.x4.shared.b16 {%0,%1,%2,%3}, [%4];"
                 : "=r"(r[0]), "=r"(r[1]), "=r"(r[2]), "=r"(r[3]) : "r"(a));
}
__device__ __forceinline__ void ldsm4t(uint32_t* r, uint32_t a) {
    asm volatile("ldmatrix.sync.aligned.m8n8.x4.trans.shared.b16 {%0,%1,%2,%3}, [%4];"
                 : "=r"(r[0]), "=r"(r[1]), "=r"(r[2]), "=r"(r[3]) : "r"(a));
}
__device__ __forceinline__ void mma16816(float* d, const uint32_t* a, const uint32_t* b) {
    asm volatile("mma.sync.aligned.m16n8k16.row.col.f32.f16.f16.f32 "
                 "{%0,%1,%2,%3}, {%4,%5,%6,%7}, {%8,%9}, {%0,%1,%2,%3};"
                 : "+f"(d[0]), "+f"(d[1]), "+f"(d[2]), "+f"(d[3])
                 : "r"(a[0]), "r"(a[1]), "r"(a[2]), "r"(a[3]), "r"(b[0]), "r"(b[1]));
}
__device__ __forceinline__ uint32_t packh2(float lo, float hi) {
    uint32_t r; asm("cvt.rn.f16x2.f32 %0, %2, %1;" : "=r"(r) : "f"(lo), "f"(hi)); return r;
}
__device__ __forceinline__ uint32_t h2ex2(uint32_t x) {
    uint32_t y; asm("ex2.approx.f16x2 %0, %1;" : "=r"(y) : "r"(x)); return y;
}
__device__ __forceinline__ void cp_tile(const __half* src, uint32_t dst_s, int tid) {
    #pragma unroll
    for (int it = 0; it < 4; ++it) {
        int idx = tid + it * 256;
        int row = idx >> 4, c16 = idx & 15;
        uint32_t d = dst_s + (row * RSH + c16 * 8) * 2;
        const void* s = src + (size_t)row * T + c16 * 8;
        asm volatile("cp.async.cg.shared.global [%0], [%1], 16;" :: "r"(d), "l"(s));
    }
}
__device__ __forceinline__ void cp_commit() {
    asm volatile("cp.async.commit_group;" ::: "memory");
}
__device__ __forceinline__ void cp_wait0() {
    asm volatile("cp.async.wait_group 0;" ::: "memory");
}

// ---- pre-pass: K,V fp32 -> fp16 ----
__global__ __launch_bounds__(256)
void cvt_kernel(const float* __restrict__ qkv, __half* __restrict__ dst)
{
    size_t idx8 = ((size_t)blockIdx.x * 256 + threadIdx.x) * 8;
    size_t bt = idx8 / (128 * 2048);
    size_t rem = idx8 % (128 * 2048);
    size_t off = bt * (192 * 2048) + 64 * 2048 + rem;
    float4 f0 = *reinterpret_cast<const float4*>(qkv + off);
    float4 f1 = *reinterpret_cast<const float4*>(qkv + off + 4);
    uint4 h;
    h.x = packh2(f0.x, f0.y);
    h.y = packh2(f0.z, f0.w);
    h.z = packh2(f1.x, f1.y);
    h.w = packh2(f1.z, f1.w);
    *reinterpret_cast<uint4*>(dst + off) = h;
}

__global__ __launch_bounds__(THREADS, 2)
void attn_hmma_kernel(const float* __restrict__ qkv, float* __restrict__ out)
{
    extern __shared__ char smem[];
    const uint32_t sb = s2u(smem);
    const int tid = threadIdx.x;
    const int lane = tid & 31, w = tid >> 5;
    const int b = blockIdx.y, t0 = blockIdx.x * BM;
    const int wm = (w >> 1) * 16;
    const int wn = (w & 1) * 64;
    const int stag = w & 3;

    const float* qb = qkv + (size_t)b * 3 * CH * T;
    const __half* kh = g_qkv16 + (size_t)b * 3 * CH * T + (size_t)CH * T;
    const __half* vh = kh + (size_t)CH * T;

    // ---- prologue ----
    cp_tile(kh, sb + OFF_K0, tid);
    cp_tile(vh, sb + OFF_V0, tid);
    cp_commit();
    #pragma unroll
    for (int it = 0; it < 4; ++it) {
        int idx = tid + it * 256;
        int c = idx >> 4, m4 = idx & 15;
        float4 f = *reinterpret_cast<const float4*>(qb + (size_t)c * T + t0 + m4 * 4);
        *reinterpret_cast<uint2*>(smem + (c * RSQ + m4 * 4) * 2) =
            make_uint2(packh2(f.x * QSCALE, f.y * QSCALE),
                       packh2(f.z * QSCALE, f.w * QSCALE));
    }
    cp_wait0();
    __syncthreads();

    const int lr = lane & 7, grp = lane >> 3;
    const int ac = lr + ((grp >= 2) ? 8 : 0);
    const int am = (grp & 1) ? 8 : 0;
    const int kc = lr + ((grp & 1) ? 8 : 0);
    const int kn = (grp >= 2) ? 8 : 0;
    const int vc = lr + ((grp >= 2) ? 8 : 0);
    const int vn = (grp & 1) ? 8 : 0;

    uint32_t ones2[2];
    ones2[0] = ones2[1] = (lane < 4) ? 0x3C003C00u : 0u;

    uint32_t qa[4][4];
    #pragma unroll
    for (int kk = 0; kk < 4; ++kk)
        ldsm4t(qa[kk], sb + ((kk * 16 + ac) * RSQ + wm + am) * 2);

    float o[8][4];
    #pragma unroll
    for (int j = 0; j < 8; ++j) o[j][0] = o[j][1] = o[j][2] = o[j][3] = 0.f;
    float oe[4] = {0.f, 0.f, 0.f, 0.f};

    for (int i = 0; i < NITER; ++i) {
        const int cur = i & 1, nxt = cur ^ 1;
        const bool more = (i + 1 < NITER);
        const uint32_t Kb = sb + OFF_K0 + cur * TSZ;
        const uint32_t Vb = sb + OFF_V0 + cur * TSZ;

        if (more) {
            cp_tile(kh + (i + 1) * BN, sb + OFF_K0 + nxt * TSZ, tid);
            cp_tile(vh + (i + 1) * BN, sb + OFF_V0 + nxt * TSZ, tid);
            cp_commit();
        }

        // ---- S(chunk 0) ----
        float s[2][4];
        s[0][0]=s[0][1]=s[0][2]=s[0][3]=0.f;
        s[1][0]=s[1][1]=s[1][2]=s[1][3]=0.f;
        {
            const int ncol = wn + (stag & 3) * 16;
            #pragma unroll
            for (int kk = 0; kk < 4; ++kk) {
                uint32_t kb4[4];
                ldsm4t(kb4, Kb + ((kk * 16 + kc) * RSH + ncol + kn) * 2);
                mma16816(s[0], qa[kk], kb4);
                mma16816(s[1], qa[kk], kb4 + 2);
            }
        }

        #pragma unroll
        for (int nn = 0; nn < 4; ++nn) {
            const int ncol  = wn + ((nn + stag) & 3) * 16;        // this chunk
            const int ncoln = wn + ((nn + 1 + stag) & 3) * 16;    // next chunk

            // ---- P = ex2(S) (consumes s; s then reusable) ----
            uint32_t pa[4];
            pa[0] = h2ex2(packh2(s[0][0], s[0][1]));
            pa[1] = h2ex2(packh2(s[0][2], s[0][3]));
            pa[2] = h2ex2(packh2(s[1][0], s[1][1]));
            pa[3] = h2ex2(packh2(s[1][2], s[1][3]));

            // ---- S(chunk nn+1): independent mma chain, overlaps PV below ----
            if (nn < 3) {
                s[0][0]=s[0][1]=s[0][2]=s[0][3]=0.f;
                s[1][0]=s[1][1]=s[1][2]=s[1][3]=0.f;
                #pragma unroll
                for (int kk = 0; kk < 4; ++kk) {
                    uint32_t kb4[4];
                    ldsm4t(kb4, Kb + ((kk * 16 + kc) * RSH + ncoln + kn) * 2);
                    mma16816(s[0], qa[kk], kb4);
                    mma16816(s[1], qa[kk], kb4 + 2);
                }
            }

            // ---- rowsum + PV(chunk nn) ----
            mma16816(oe, pa, ones2);
            #pragma unroll
            for (int cc = 0; cc < 4; ++cc) {
                uint32_t vb4[4];
                ldsm4(vb4, Vb + ((cc * 16 + vc) * RSH + ncol + vn) * 2);
                mma16816(o[2 * cc],     pa, vb4);
                mma16816(o[2 * cc + 1], pa, vb4 + 2);
            }
        }

        if (more) cp_wait0();
        __syncthreads();
    }

    // ---- epilogue: cross-half reduction + normalize + store ----
    {
        float* Os = reinterpret_cast<float*>(smem + ((w & 1) ? OFF_OS1 : OFF_OS0));
        const int cq = 2 * (lane & 3);
        const int r0 = wm + (lane >> 2), r1 = r0 + 8;
        #pragma unroll
        for (int j = 0; j < 8; ++j) {
            const int c = (j >> 1) * 16 + (j & 1) * 8 + cq;
            Os[c * 68 + r0]       = o[j][0];
            Os[(c + 1) * 68 + r0] = o[j][1];
            Os[c * 68 + r1]       = o[j][2];
            Os[(c + 1) * 68 + r1] = o[j][3];
        }
        float* SU = reinterpret_cast<float*>(smem + OFF_SUM) + (w & 1) * 64;
        if ((lane & 3) == 0) {
            SU[r0]     = oe[0];
            SU[r0 + 8] = oe[2];
        }
        __syncthreads();

        float* S0 = reinterpret_cast<float*>(smem + OFF_SUM);
        float* IV = reinterpret_cast<float*>(smem + OFF_INV);
        if (tid < 64) IV[tid] = 1.0f / (S0[tid] + S0[64 + tid]);
        __syncthreads();

        const float* Os0 = reinterpret_cast<const float*>(smem + OFF_OS0);
        const float* Os1 = reinterpret_cast<const float*>(smem + OFF_OS1);
        float* ob = out + (size_t)b * CH * T;
        #pragma unroll
        for (int it = 0; it < 4; ++it) {
            int idx = tid + it * 256;
            int c = idx >> 4, m4 = idx & 15;
            float4 a = *reinterpret_cast<const float4*>(&Os0[c * 68 + m4 * 4]);
            float4 d = *reinterpret_cast<const float4*>(&Os1[c * 68 + m4 * 4]);
            float4 iv = *reinterpret_cast<const float4*>(&IV[m4 * 4]);
            float4 r = make_float4((a.x + d.x) * iv.x, (a.y + d.y) * iv.y,
                                   (a.z + d.z) * iv.z, (a.w + d.w) * iv.w);
            *reinterpret_cast<float4*>(ob + (size_t)c * T + t0 + m4 * 4) = r;
        }
    }
}

extern "C" void kernel_launch(void* const* d_in, const int* in_sizes, int n_in,
                              void* d_out, int out_size)
{
    (void)in_sizes; (void)n_in; (void)out_size;
    const float* qkv = (const float*)d_in[0];
    float* out = (float*)d_out;

    __half* scratch = nullptr;
    cudaGetSymbolAddress((void**)&scratch, g_qkv16);

    cudaFuncSetAttribute(attn_hmma_kernel,
                         cudaFuncAttributeMaxDynamicSharedMemorySize, SMEM_TOTAL);

    cvt_kernel<<<4096, 256>>>(qkv, scratch);
    dim3 grid(T / BM, 32);
    attn_hmma_kernel<<<grid, THREADS, SMEM_TOTAL>>>(qkv, out);
}